// round 1
// baseline (speedup 1.0000x reference)
#include <cuda_runtime.h>
#include <math.h>

#define BATCH 8192
#define DIM   512
#define MEM   1000
#define MEMP  1024
#define HEADS 8
#define DH    64

// ---------------- scratch (static device allocations, allowed) ----------------
__device__ float g_h[BATCH*DIM];
__device__ float g_hn[BATCH*DIM];
__device__ float g_enc[BATCH*DIM];
__device__ float g_q[BATCH*DIM];
__device__ float g_ctx[BATCH*DIM];
__device__ float g_fused[BATCH*DIM];
__device__ float g_k[MEMP*DIM];
__device__ float g_v[MEMP*DIM];
__device__ int   g_midx[BATCH];
__device__ int   g_mcount;

// ---------------- generic GEMM: C[i,j] = sum_k A[i,k] * W[j,k] + bias[j] -------
// A: [Mrows, K] (row stride lda; optional A2 holds cols [512,K) with stride 16)
// W: [512, K] row-major. C: [Mrows, 512].
// EPI: 0 = none, 1 = relu, 2 = fuse: C = 0.7*F + 0.3*(acc+bias)
template<int EPI>
__global__ void __launch_bounds__(256) gemm_tn(
    const float* __restrict__ A, const float* __restrict__ A2,
    const float* __restrict__ W, const float* __restrict__ bias,
    const float* __restrict__ F,
    float* __restrict__ C, int Mrows, int K, int lda)
{
    __shared__ float As[128][16];
    __shared__ float Ws[16][132];

    const int bx = blockIdx.x;           // n tile (0..3)
    const int by = blockIdx.y;           // m tile
    const int tid = threadIdx.x;
    const int tx = tid & 15, ty = tid >> 4;
    const int row0 = by * 128;

    float acc[8][8];
    #pragma unroll
    for (int i = 0; i < 8; ++i)
        #pragma unroll
        for (int j = 0; j < 8; ++j) acc[i][j] = 0.f;

    const int ntiles = K >> 4;
    for (int kt = 0; kt < ntiles; ++kt) {
        const int kbase = kt << 4;
        // load A tile (128 x 16)
        #pragma unroll
        for (int t = 0; t < 2; ++t) {
            int vid = tid + t * 256;
            int r = vid >> 2, kv = vid & 3;
            int grow = row0 + r;
            float4 a = make_float4(0.f, 0.f, 0.f, 0.f);
            if (grow < Mrows) {
                if (A2 != nullptr && kbase >= 512)
                    a = *(const float4*)(A2 + (size_t)grow * 16 + (kbase - 512) + kv * 4);
                else
                    a = *(const float4*)(A + (size_t)grow * lda + kbase + kv * 4);
            }
            *(float4*)&As[r][kv * 4] = a;
        }
        // load W tile (transposed into Ws[k][n])
        #pragma unroll
        for (int t = 0; t < 2; ++t) {
            int vid = tid + t * 256;
            int r = vid >> 2, kv = vid & 3;
            int wrow = bx * 128 + r;
            float4 w = *(const float4*)(W + (size_t)wrow * K + kbase + kv * 4);
            Ws[kv * 4 + 0][r] = w.x;
            Ws[kv * 4 + 1][r] = w.y;
            Ws[kv * 4 + 2][r] = w.z;
            Ws[kv * 4 + 3][r] = w.w;
        }
        __syncthreads();

        #pragma unroll
        for (int c = 0; c < 16; ++c) {
            float af[8], bf[8];
            #pragma unroll
            for (int i = 0; i < 8; ++i) af[i] = As[ty * 8 + i][c];
            float4 b0 = *(const float4*)&Ws[c][tx * 8];
            float4 b1 = *(const float4*)&Ws[c][tx * 8 + 4];
            bf[0] = b0.x; bf[1] = b0.y; bf[2] = b0.z; bf[3] = b0.w;
            bf[4] = b1.x; bf[5] = b1.y; bf[6] = b1.z; bf[7] = b1.w;
            #pragma unroll
            for (int i = 0; i < 8; ++i)
                #pragma unroll
                for (int j = 0; j < 8; ++j)
                    acc[i][j] = fmaf(af[i], bf[j], acc[i][j]);
        }
        __syncthreads();
    }

    // epilogue
    #pragma unroll
    for (int i = 0; i < 8; ++i) {
        int grow = row0 + ty * 8 + i;
        if (grow >= Mrows) continue;
        #pragma unroll
        for (int j = 0; j < 8; j += 4) {
            int gcol = bx * 128 + tx * 8 + j;
            float4 bv = *(const float4*)(bias + gcol);
            float4 v;
            v.x = acc[i][j + 0] + bv.x;
            v.y = acc[i][j + 1] + bv.y;
            v.z = acc[i][j + 2] + bv.z;
            v.w = acc[i][j + 3] + bv.w;
            if (EPI == 1) {
                v.x = fmaxf(v.x, 0.f); v.y = fmaxf(v.y, 0.f);
                v.z = fmaxf(v.z, 0.f); v.w = fmaxf(v.w, 0.f);
            } else if (EPI == 2) {
                float4 f = *(const float4*)(F + (size_t)grow * 512 + gcol);
                v.x = 0.7f * f.x + 0.3f * v.x;
                v.y = 0.7f * f.y + 0.3f * v.y;
                v.z = 0.7f * f.z + 0.3f * v.z;
                v.w = 0.7f * f.w + 0.3f * v.w;
            }
            *(float4*)(C + (size_t)grow * 512 + gcol) = v;
        }
    }
}

// ---------------- LayerNorm over D=512, one block (128 thr) per row ------------
__global__ void __launch_bounds__(128) ln_kernel(
    const float* __restrict__ x, const float* __restrict__ g,
    const float* __restrict__ b, float* __restrict__ y)
{
    const int row = blockIdx.x;
    const int tid = threadIdx.x;
    float4 v = *(const float4*)(x + (size_t)row * 512 + tid * 4);

    __shared__ float red[4];
    float s = v.x + v.y + v.z + v.w;
    #pragma unroll
    for (int o = 16; o > 0; o >>= 1) s += __shfl_xor_sync(0xffffffffu, s, o);
    if ((tid & 31) == 0) red[tid >> 5] = s;
    __syncthreads();
    float mean = (red[0] + red[1] + red[2] + red[3]) * (1.f / 512.f);
    __syncthreads();

    float dx = v.x - mean, dy = v.y - mean, dz = v.z - mean, dw = v.w - mean;
    float ss = dx * dx + dy * dy + dz * dz + dw * dw;
    #pragma unroll
    for (int o = 16; o > 0; o >>= 1) ss += __shfl_xor_sync(0xffffffffu, ss, o);
    if ((tid & 31) == 0) red[tid >> 5] = ss;
    __syncthreads();
    float var = (red[0] + red[1] + red[2] + red[3]) * (1.f / 512.f);
    float inv = rsqrtf(var + 1e-5f);

    float4 gg = *(const float4*)(g + tid * 4);
    float4 bb = *(const float4*)(b + tid * 4);
    float4 o;
    o.x = dx * inv * gg.x + bb.x;
    o.y = dy * inv * gg.y + bb.y;
    o.z = dz * inv * gg.z + bb.z;
    o.w = dw * inv * gg.w + bb.w;
    *(float4*)(y + (size_t)row * 512 + tid * 4) = o;
}

// ---------------- fused cross-attention (flash-style) --------------------------
// grid (8, 128); block 256. Each block: one head, 64 batch rows.
// smem: Qs[64][68] (d-major), Ks[64][68] (d-major, aliased by P[b][m]), Vs[64][68].
#define ATT_STRIDE 68
#define ATT_SMEM (3 * 64 * ATT_STRIDE * 4)
__global__ void __launch_bounds__(256) attn_kernel(
    const float* __restrict__ Q, const float* __restrict__ Kb,
    const float* __restrict__ Vb, float* __restrict__ ctx)
{
    extern __shared__ float sm[];
    float* Qs = sm;
    float* Ks = sm + 64 * ATT_STRIDE;   // also serves as P after S-compute
    float* Vs = sm + 2 * 64 * ATT_STRIDE;

    const int h = blockIdx.x;
    const int b0 = blockIdx.y * 64;
    const int tid = threadIdx.x;
    const int tx = tid & 15, ty = tid >> 4;

    // load Q tile transposed: Qs[d][b_local]
    #pragma unroll
    for (int t = 0; t < 4; ++t) {
        int vid = tid + t * 256;
        int r = vid >> 4, vv = vid & 15;
        float4 qv = *(const float4*)(Q + (size_t)(b0 + r) * 512 + h * 64 + vv * 4);
        Qs[(vv * 4 + 0) * ATT_STRIDE + r] = qv.x;
        Qs[(vv * 4 + 1) * ATT_STRIDE + r] = qv.y;
        Qs[(vv * 4 + 2) * ATT_STRIDE + r] = qv.z;
        Qs[(vv * 4 + 3) * ATT_STRIDE + r] = qv.w;
    }

    float rmax[4], rsum[4], acc[4][4];
    #pragma unroll
    for (int i = 0; i < 4; ++i) {
        rmax[i] = -1e30f; rsum[i] = 0.f;
        #pragma unroll
        for (int j = 0; j < 4; ++j) acc[i][j] = 0.f;
    }

    for (int m0 = 0; m0 < MEMP; m0 += 64) {
        __syncthreads();   // previous iteration's P/V readers done
        // load K chunk transposed Ks[d][m], V chunk natural Vs[m][d]
        #pragma unroll
        for (int t = 0; t < 4; ++t) {
            int vid = tid + t * 256;
            int mr = vid >> 4, vv = vid & 15;
            int gm = m0 + mr;
            float4 k4 = make_float4(0.f, 0.f, 0.f, 0.f);
            float4 v4 = make_float4(0.f, 0.f, 0.f, 0.f);
            if (gm < MEM) {
                k4 = *(const float4*)(Kb + (size_t)gm * 512 + h * 64 + vv * 4);
                v4 = *(const float4*)(Vb + (size_t)gm * 512 + h * 64 + vv * 4);
            }
            Ks[(vv * 4 + 0) * ATT_STRIDE + mr] = k4.x;
            Ks[(vv * 4 + 1) * ATT_STRIDE + mr] = k4.y;
            Ks[(vv * 4 + 2) * ATT_STRIDE + mr] = k4.z;
            Ks[(vv * 4 + 3) * ATT_STRIDE + mr] = k4.w;
            *(float4*)&Vs[mr * ATT_STRIDE + vv * 4] = v4;
        }
        __syncthreads();

        // S[b][m] tile, 4x4 per thread
        float s[4][4];
        #pragma unroll
        for (int i = 0; i < 4; ++i)
            #pragma unroll
            for (int j = 0; j < 4; ++j) s[i][j] = 0.f;
        #pragma unroll 8
        for (int d = 0; d < 64; ++d) {
            float4 aa = *(const float4*)&Qs[d * ATT_STRIDE + ty * 4];
            float4 bb = *(const float4*)&Ks[d * ATT_STRIDE + tx * 4];
            float a_[4] = {aa.x, aa.y, aa.z, aa.w};
            float b_[4] = {bb.x, bb.y, bb.z, bb.w};
            #pragma unroll
            for (int i = 0; i < 4; ++i)
                #pragma unroll
                for (int j = 0; j < 4; ++j)
                    s[i][j] = fmaf(a_[i], b_[j], s[i][j]);
        }
        #pragma unroll
        for (int i = 0; i < 4; ++i)
            #pragma unroll
            for (int j = 0; j < 4; ++j) {
                s[i][j] *= 0.125f;                       // 1/sqrt(64)
                if (m0 + tx * 4 + j >= MEM) s[i][j] = -1e30f;
            }
        __syncthreads();   // done reading Ks; safe to overwrite as P

        // online softmax per row; write P into Ks region
        #pragma unroll
        for (int i = 0; i < 4; ++i) {
            float mx = fmaxf(fmaxf(s[i][0], s[i][1]), fmaxf(s[i][2], s[i][3]));
            #pragma unroll
            for (int o = 1; o < 16; o <<= 1) mx = fmaxf(mx, __shfl_xor_sync(0xffffffffu, mx, o));
            float nm = fmaxf(rmax[i], mx);
            float corr = __expf(rmax[i] - nm);
            rmax[i] = nm;
            float ps = 0.f;
            #pragma unroll
            for (int j = 0; j < 4; ++j) {
                float p = __expf(s[i][j] - nm);
                s[i][j] = p; ps += p;
            }
            #pragma unroll
            for (int o = 1; o < 16; o <<= 1) ps += __shfl_xor_sync(0xffffffffu, ps, o);
            rsum[i] = rsum[i] * corr + ps;
            #pragma unroll
            for (int j = 0; j < 4; ++j) acc[i][j] *= corr;
            *(float4*)&Ks[(ty * 4 + i) * ATT_STRIDE + tx * 4] =
                make_float4(s[i][0], s[i][1], s[i][2], s[i][3]);
        }
        __syncthreads();

        // acc += P * V
        #pragma unroll 8
        for (int m = 0; m < 64; ++m) {
            float4 vv4 = *(const float4*)&Vs[m * ATT_STRIDE + tx * 4];
            float v_[4] = {vv4.x, vv4.y, vv4.z, vv4.w};
            #pragma unroll
            for (int i = 0; i < 4; ++i) {
                float p = Ks[(ty * 4 + i) * ATT_STRIDE + m];
                #pragma unroll
                for (int j = 0; j < 4; ++j)
                    acc[i][j] = fmaf(p, v_[j], acc[i][j]);
            }
        }
    }

    #pragma unroll
    for (int i = 0; i < 4; ++i) {
        float inv = 1.f / rsum[i];
        float4 o = make_float4(acc[i][0] * inv, acc[i][1] * inv,
                               acc[i][2] * inv, acc[i][3] * inv);
        *(float4*)(ctx + (size_t)(b0 + ty * 4 + i) * 512 + h * 64 + tx * 4) = o;
    }
}

// ---------------- quality head: one block (128 thr) per row --------------------
__global__ void __launch_bounds__(128) quality_kernel(
    const float* __restrict__ ns, const float* __restrict__ w1,
    const float* __restrict__ b1, const float* __restrict__ w2,
    const float* __restrict__ b2, float* __restrict__ qout)
{
    const int row = blockIdx.x;
    const int j = threadIdx.x;
    __shared__ float xs[512];
    *(float4*)&xs[j * 4] = *(const float4*)(ns + (size_t)row * 512 + j * 4);
    __syncthreads();

    float s = 0.f;
    const float* wr = w1 + (size_t)j * 512;
    #pragma unroll 8
    for (int k = 0; k < 512; k += 4) {
        float4 w = *(const float4*)(wr + k);
        s += xs[k] * w.x + xs[k + 1] * w.y + xs[k + 2] * w.z + xs[k + 3] * w.w;
    }
    s = fmaxf(s + b1[j], 0.f) * w2[j];

    __shared__ float red[4];
    #pragma unroll
    for (int o = 16; o > 0; o >>= 1) s += __shfl_xor_sync(0xffffffffu, s, o);
    if ((j & 31) == 0) red[j >> 5] = s;
    __syncthreads();
    if (j == 0) {
        float t = red[0] + red[1] + red[2] + red[3] + b2[0];
        qout[row] = 1.f / (1.f + expf(-t));
    }
}

// ---------------- stable compaction of mask = quality > 0.7 --------------------
__global__ void __launch_bounds__(256) compact_kernel(
    const float* __restrict__ quality, int* __restrict__ midx, int* __restrict__ mcount)
{
    const int tid = threadIdx.x;
    const int base = tid * 32;
    int cnt = 0;
    for (int i = 0; i < 32; ++i) cnt += (quality[base + i] > 0.7f) ? 1 : 0;
    __shared__ int sc[256];
    __shared__ int offs[256];
    sc[tid] = cnt;
    __syncthreads();
    if (tid == 0) {
        int run = 0;
        for (int t = 0; t < 256; ++t) { offs[t] = run; run += sc[t]; }
        *mcount = run;
    }
    __syncthreads();
    int o = offs[tid];
    for (int i = 0; i < 32; ++i)
        if (quality[base + i] > 0.7f) midx[o++] = base + i;
}

// ---------------- memory bank EMA replay (sequential semantics) ----------------
__global__ void __launch_bounds__(128) memupd_kernel(
    const float* __restrict__ wm, const float* __restrict__ ns,
    const int* __restrict__ upd, const int* __restrict__ midx,
    const int* __restrict__ mcount, float* __restrict__ outmem)
{
    const int m = blockIdx.x;
    const int d = threadIdx.x * 4;
    float4 v = *(const float4*)(wm + (size_t)m * 512 + d);
    const int cnt = *mcount;
    for (int jj = 0; jj < cnt; ++jj) {
        int i = midx[jj];
        if (upd[i] == m) {
            float4 s = *(const float4*)(ns + (size_t)i * 512 + d);
            v.x = 0.9f * v.x + 0.1f * s.x;
            v.y = 0.9f * v.y + 0.1f * s.y;
            v.z = 0.9f * v.z + 0.1f * s.z;
            v.w = 0.9f * v.w + 0.1f * s.w;
        }
    }
    *(float4*)(outmem + (size_t)m * 512 + d) = v;
}

// ---------------- host launcher -----------------------------------------------
extern "C" void kernel_launch(void* const* d_in, const int* in_sizes, int n_in,
                              void* d_out, int out_size)
{
    const float* obs    = (const float*)d_in[0];
    const float* ego    = (const float*)d_in[1];
    const float* wm     = (const float*)d_in[2];
    const float* enc_w1 = (const float*)d_in[3];
    const float* enc_b1 = (const float*)d_in[4];
    const float* enc_g  = (const float*)d_in[5];
    const float* enc_be = (const float*)d_in[6];
    const float* enc_w2 = (const float*)d_in[7];
    const float* enc_b2 = (const float*)d_in[8];
    const float* wq     = (const float*)d_in[9];
    const float* bq     = (const float*)d_in[10];
    const float* wk     = (const float*)d_in[11];
    const float* bk     = (const float*)d_in[12];
    const float* wv     = (const float*)d_in[13];
    const float* bv     = (const float*)d_in[14];
    const float* wo     = (const float*)d_in[15];
    const float* bo     = (const float*)d_in[16];
    const float* tr_w1  = (const float*)d_in[17];
    const float* tr_b1  = (const float*)d_in[18];
    const float* tr_g   = (const float*)d_in[19];
    const float* tr_be  = (const float*)d_in[20];
    const float* tr_w2  = (const float*)d_in[21];
    const float* tr_b2  = (const float*)d_in[22];
    const float* q_w1   = (const float*)d_in[23];
    const float* q_b1   = (const float*)d_in[24];
    const float* q_w2   = (const float*)d_in[25];
    const float* q_b2   = (const float*)d_in[26];
    const int*   uidx   = (const int*)d_in[27];

    float* out        = (float*)d_out;
    float* next_state = out;
    float* quality    = out + (size_t)BATCH * DIM;
    float* outmem     = quality + BATCH;

    float *h, *hn, *enc, *qb, *ctx, *fused, *kb, *vb;
    int *midx, *mcount;
    cudaGetSymbolAddress((void**)&h,     g_h);
    cudaGetSymbolAddress((void**)&hn,    g_hn);
    cudaGetSymbolAddress((void**)&enc,   g_enc);
    cudaGetSymbolAddress((void**)&qb,    g_q);
    cudaGetSymbolAddress((void**)&ctx,   g_ctx);
    cudaGetSymbolAddress((void**)&fused, g_fused);
    cudaGetSymbolAddress((void**)&kb,    g_k);
    cudaGetSymbolAddress((void**)&vb,    g_v);
    cudaGetSymbolAddress((void**)&midx,  g_midx);
    cudaGetSymbolAddress((void**)&mcount, g_mcount);

    dim3 gBig(4, 64), gMem(4, 8);

    // encoder
    gemm_tn<1><<<gBig, 256>>>(obs, nullptr, enc_w1, enc_b1, nullptr, h, BATCH, 512, 512);
    ln_kernel<<<BATCH, 128>>>(h, enc_g, enc_be, hn);
    gemm_tn<0><<<gBig, 256>>>(hn, nullptr, enc_w2, enc_b2, nullptr, enc, BATCH, 512, 512);
    // projections
    gemm_tn<0><<<gBig, 256>>>(enc, nullptr, wq, bq, nullptr, qb, BATCH, 512, 512);
    gemm_tn<0><<<gMem, 256>>>(wm, nullptr, wk, bk, nullptr, kb, MEM, 512, 512);
    gemm_tn<0><<<gMem, 256>>>(wm, nullptr, wv, bv, nullptr, vb, MEM, 512, 512);
    // attention
    cudaFuncSetAttribute(attn_kernel, cudaFuncAttributeMaxDynamicSharedMemorySize, ATT_SMEM);
    attn_kernel<<<dim3(HEADS, BATCH / 64), 256, ATT_SMEM>>>(qb, kb, vb, ctx);
    // out projection + fuse (0.7*enc + 0.3*mem_states)
    gemm_tn<2><<<gBig, 256>>>(ctx, nullptr, wo, bo, enc, fused, BATCH, 512, 512);
    // transition (K = 528 via concat with ego motion)
    gemm_tn<1><<<gBig, 256>>>(fused, ego, tr_w1, tr_b1, nullptr, h, BATCH, 528, 512);
    ln_kernel<<<BATCH, 128>>>(h, tr_g, tr_be, hn);
    gemm_tn<0><<<gBig, 256>>>(hn, nullptr, tr_w2, tr_b2, nullptr, next_state, BATCH, 512, 512);
    // quality head
    quality_kernel<<<BATCH, 128>>>(next_state, q_w1, q_b1, q_w2, q_b2, quality);
    // memory bank update (exact sequential EMA semantics)
    compact_kernel<<<1, 256>>>(quality, midx, mcount);
    memupd_kernel<<<MEM, 128>>>(wm, next_state, uidx, midx, mcount, outmem);
}

// round 3
// speedup vs baseline: 3.6237x; 3.6237x over previous
#include <cuda_runtime.h>
#include <math.h>
#include <stdint.h>

#define BATCH 8192
#define DIM   512
#define MEM   1000
#define MEMP  1024
#define HEADS 8
#define DH    64

// ==================== helpers ====================
__device__ __forceinline__ uint32_t smem_u32(const void* p) {
    uint32_t a;
    asm("{ .reg .u64 t; cvta.to.shared.u64 t, %1; cvt.u32.u64 %0, t; }" : "=r"(a) : "l"(p));
    return a;
}
__device__ __forceinline__ uint32_t f2tf(float x) {
    uint32_t u; asm("cvt.rna.tf32.f32 %0, %1;" : "=r"(u) : "f"(x)); return u;
}
__device__ __forceinline__ void mma_tf32(float* c, uint32_t a0, uint32_t a1,
                                         uint32_t a2, uint32_t a3,
                                         uint32_t b0, uint32_t b1) {
    asm volatile(
        "mma.sync.aligned.m16n8k8.row.col.f32.tf32.tf32.f32 "
        "{%0,%1,%2,%3}, {%4,%5,%6,%7}, {%8,%9}, {%0,%1,%2,%3};"
        : "+f"(c[0]), "+f"(c[1]), "+f"(c[2]), "+f"(c[3])
        : "r"(a0), "r"(a1), "r"(a2), "r"(a3), "r"(b0), "r"(b1));
}
__device__ __forceinline__ void cp_async16(uint32_t dst, const void* src, int srcsize) {
    asm volatile("cp.async.cg.shared.global [%0], [%1], 16, %2;"
                 :: "r"(dst), "l"(src), "r"(srcsize));
}
#define CP_COMMIT() asm volatile("cp.async.commit_group;" ::: "memory")
#define CP_WAIT(N)  asm volatile("cp.async.wait_group %0;" :: "n"(N) : "memory")

// ==================== scratch ====================
__device__ float g_h[BATCH*DIM];
__device__ float g_hn[BATCH*DIM];
__device__ float g_enc[BATCH*DIM];
__device__ float g_q[BATCH*DIM];
__device__ float g_ctx[BATCH*DIM];
__device__ float g_fused[BATCH*DIM];
__device__ float g_k[MEMP*DIM];
__device__ float g_v[MEMP*DIM];
__device__ int   g_midx[BATCH];
__device__ int   g_mcount;

// ==================== tf32 mma GEMM ====================
// C[i,j] = sum_k A[i,k]*W[j,k] (+bias). 128x128 CTA tile, BK=32, double buffer.
// A2: optional 16 extra K-cols (ego concat, row stride 16), zero-padded to chunk.
// EPI: 0 none, 1 relu, 2 fuse (0.7*F + 0.3*(acc+bias)), 3 quality head.
#define GS 36                 // smem K stride (floats): banks 4g+t conflict-free
#define GEMM_SMEM (4 * 4608 * 4)   // As[2][128*36] + Ws[2][128*36]

template<int EPI>
__global__ void __launch_bounds__(256) gemm_mma(
    const float* __restrict__ A, const float* __restrict__ A2,
    const float* __restrict__ W, const float* __restrict__ bias,
    const float* __restrict__ F, const float* __restrict__ w2,
    const float* __restrict__ b2, float* __restrict__ C,
    int Mrows, int Kw, int Ktiles)
{
    extern __shared__ float sm[];
    float* Asm = sm;            // 2 x 4608
    float* Wsm = sm + 9216;     // 2 x 4608
    const uint32_t sA = smem_u32(Asm);
    const uint32_t sW = smem_u32(Wsm);

    const int tid = threadIdx.x;
    const int wid = tid >> 5, lane = tid & 31;
    const int g = lane >> 2, t = lane & 3;
    const int wm = wid & 1, wn = wid >> 1;       // warp tile: rows wm*64, cols wn*32
    const int row0 = blockIdx.y * 128;
    const int col0 = blockIdx.x * 128;

    float acc[4][4][4];
    #pragma unroll
    for (int mf = 0; mf < 4; ++mf)
        #pragma unroll
        for (int nf = 0; nf < 4; ++nf)
            #pragma unroll
            for (int c = 0; c < 4; ++c) acc[mf][nf][c] = 0.f;

    // ---- loader for K-chunk t into buffer buf ----
    auto load_chunk = [&](int ct, int buf) {
        const int kbase = ct * 32;
        #pragma unroll
        for (int it = 0; it < 4; ++it) {
            int vid = tid + it * 256;          // 0..1023
            int r = vid >> 3, q = vid & 7;
            int kel = kbase + q * 4;
            // A
            const float* srcA = A;
            int szA = 0;
            int grow = row0 + r;
            if (grow < Mrows) {
                if (kel < 512) { srcA = A + (size_t)grow * 512 + kel; szA = 16; }
                else if (A2 != nullptr && kel < 528) {
                    srcA = A2 + (size_t)grow * 16 + (kel - 512); szA = 16;
                }
            }
            cp_async16(sA + (buf * 4608 + r * GS + q * 4) * 4, srcA, szA);
            // W
            const float* srcW = W + (size_t)(col0 + r) * Kw + kel;
            int szW = (kel < Kw) ? 16 : 0;
            cp_async16(sW + (buf * 4608 + r * GS + q * 4) * 4, srcW, szW);
        }
        CP_COMMIT();
    };

    load_chunk(0, 0);

    for (int ct = 0; ct < Ktiles; ++ct) {
        const int buf = ct & 1;
        if (ct + 1 < Ktiles) { load_chunk(ct + 1, (ct + 1) & 1); CP_WAIT(1); }
        else                 { CP_WAIT(0); }
        __syncthreads();

        const float* Ab = Asm + buf * 4608 + (wm * 64) * GS;
        const float* Wb = Wsm + buf * 4608 + (wn * 32) * GS;
        #pragma unroll
        for (int ks = 0; ks < 4; ++ks) {
            const int k0 = ks * 8;
            uint32_t af[4][4];
            #pragma unroll
            for (int mf = 0; mf < 4; ++mf) {
                const float* ar = Ab + (mf * 16) * GS + k0;
                af[mf][0] = f2tf(ar[(g    ) * GS + t    ]);
                af[mf][1] = f2tf(ar[(g + 8) * GS + t    ]);
                af[mf][2] = f2tf(ar[(g    ) * GS + t + 4]);
                af[mf][3] = f2tf(ar[(g + 8) * GS + t + 4]);
            }
            #pragma unroll
            for (int nf = 0; nf < 4; ++nf) {
                const float* wr = Wb + (nf * 8 + g) * GS + k0;
                uint32_t b0 = f2tf(wr[t]);
                uint32_t b1 = f2tf(wr[t + 4]);
                #pragma unroll
                for (int mf = 0; mf < 4; ++mf)
                    mma_tf32(acc[mf][nf], af[mf][0], af[mf][1], af[mf][2], af[mf][3], b0, b1);
            }
        }
        __syncthreads();
    }

    if (EPI != 3) {
        #pragma unroll
        for (int mf = 0; mf < 4; ++mf) {
            #pragma unroll
            for (int r01 = 0; r01 < 2; ++r01) {
                int grow = row0 + wm * 64 + mf * 16 + g + r01 * 8;
                if (grow >= Mrows) continue;
                #pragma unroll
                for (int nf = 0; nf < 4; ++nf) {
                    int gcol = col0 + wn * 32 + nf * 8 + 2 * t;
                    float v0 = acc[mf][nf][r01 * 2 + 0] + bias[gcol];
                    float v1 = acc[mf][nf][r01 * 2 + 1] + bias[gcol + 1];
                    if (EPI == 1) { v0 = fmaxf(v0, 0.f); v1 = fmaxf(v1, 0.f); }
                    else if (EPI == 2) {
                        const float* fp = F + (size_t)grow * 512 + gcol;
                        v0 = 0.7f * fp[0] + 0.3f * v0;
                        v1 = 0.7f * fp[1] + 0.3f * v1;
                    }
                    float2* dst = (float2*)(C + (size_t)grow * 512 + gcol);
                    *dst = make_float2(v0, v1);
                }
            }
        }
    } else {
        // quality head: sigmoid(b2 + sum_c relu(acc + b1[c]) * w2[c]); N tile = 128 (col0=0)
        float* qpart = sm;   // 128 x 17 floats, reuse As (all compute done)
        __syncthreads();
        #pragma unroll
        for (int mf = 0; mf < 4; ++mf) {
            #pragma unroll
            for (int r01 = 0; r01 < 2; ++r01) {
                float s = 0.f;
                #pragma unroll
                for (int nf = 0; nf < 4; ++nf) {
                    int c = wn * 32 + nf * 8 + 2 * t;
                    float h0 = fmaxf(acc[mf][nf][r01 * 2 + 0] + bias[c], 0.f);
                    float h1 = fmaxf(acc[mf][nf][r01 * 2 + 1] + bias[c + 1], 0.f);
                    s += h0 * w2[c] + h1 * w2[c + 1];
                }
                int rl = wm * 64 + mf * 16 + r01 * 8 + g;
                qpart[rl * 17 + wn * 4 + t] = s;
            }
        }
        __syncthreads();
        if (tid < 128) {
            float s = b2[0];
            #pragma unroll
            for (int i = 0; i < 16; ++i) s += qpart[tid * 17 + i];
            C[row0 + tid] = 1.f / (1.f + expf(-s));
        }
    }
}

// ==================== tf32 mma flash attention ====================
// grid (HEADS, BATCH/128); 256 threads = 8 warps; warp w owns q-rows w*16..w*16+15.
#define QS 68
#define VS 72
#define ATT_SMEM ((128*QS + 64*QS + 128*QS + 64*VS) * 4)
__global__ void __launch_bounds__(256) attn_mma(
    const float* __restrict__ Q, const float* __restrict__ Kb,
    const float* __restrict__ Vb, float* __restrict__ ctx)
{
    extern __shared__ float sm[];
    float* Qs = sm;                       // 128 x 68
    float* Ks = Qs + 128 * QS;            // 64 x 68
    float* Ps = Ks + 64 * QS;             // 128 x 68
    float* Vs = Ps + 128 * QS;            // 64 x 72
    const uint32_t sK = smem_u32(Ks);
    const uint32_t sV = smem_u32(Vs);

    const int h = blockIdx.x;
    const int b0 = blockIdx.y * 128;
    const int tid = threadIdx.x;
    const int wid = tid >> 5, lane = tid & 31;
    const int g = lane >> 2, t = lane & 3;
    const int qr = wid * 16;              // warp's local q-row base

    // load Q tile (always in-bounds)
    #pragma unroll
    for (int it = 0; it < 8; ++it) {
        int vid = tid + it * 256;         // 2048 = 128 rows x 16 float4
        int r = vid >> 4, q = vid & 15;
        float4 v = *(const float4*)(Q + (size_t)(b0 + r) * 512 + h * 64 + q * 4);
        *(float4*)&Qs[r * QS + q * 4] = v;
    }

    float oacc[8][4];
    float rmax[2] = {-1e30f, -1e30f}, rsum[2] = {0.f, 0.f};
    #pragma unroll
    for (int nf = 0; nf < 8; ++nf)
        #pragma unroll
        for (int c = 0; c < 4; ++c) oacc[nf][c] = 0.f;

    for (int m0 = 0; m0 < MEMP; m0 += 64) {
        __syncthreads();   // prior chunk's K/V readers done
        #pragma unroll
        for (int it = 0; it < 4; ++it) {
            int vid = tid + it * 256;     // 1024 = 64 rows x 16 float4
            int r = vid >> 4, q = vid & 15;
            int gm = m0 + r;
            int sz = (gm < MEM) ? 16 : 0;
            const float* src = Kb + (size_t)gm * 512 + h * 64 + q * 4;
            cp_async16(sK + (r * QS + q * 4) * 4, src, sz);
            const float* srcv = Vb + (size_t)gm * 512 + h * 64 + q * 4;
            cp_async16(sV + (r * VS + q * 4) * 4, srcv, sz);
        }
        CP_COMMIT();
        CP_WAIT(0);
        __syncthreads();

        // ---- S = Q K^T (64 mem cols) ----
        float sacc[8][4];
        #pragma unroll
        for (int nf = 0; nf < 8; ++nf)
            #pragma unroll
            for (int c = 0; c < 4; ++c) sacc[nf][c] = 0.f;
        #pragma unroll
        for (int ks = 0; ks < 8; ++ks) {
            int k0 = ks * 8;
            uint32_t a0 = f2tf(Qs[(qr + g    ) * QS + k0 + t    ]);
            uint32_t a1 = f2tf(Qs[(qr + g + 8) * QS + k0 + t    ]);
            uint32_t a2 = f2tf(Qs[(qr + g    ) * QS + k0 + t + 4]);
            uint32_t a3 = f2tf(Qs[(qr + g + 8) * QS + k0 + t + 4]);
            #pragma unroll
            for (int nf = 0; nf < 8; ++nf) {
                uint32_t b0 = f2tf(Ks[(nf * 8 + g) * QS + k0 + t    ]);
                uint32_t b1 = f2tf(Ks[(nf * 8 + g) * QS + k0 + t + 4]);
                mma_tf32(sacc[nf], a0, a1, a2, a3, b0, b1);
            }
        }

        // ---- online softmax on fragments; P -> Ps (warp-private rows) ----
        #pragma unroll
        for (int r01 = 0; r01 < 2; ++r01) {
            float mx = -1e30f;
            #pragma unroll
            for (int nf = 0; nf < 8; ++nf) {
                #pragma unroll
                for (int c = 0; c < 2; ++c) {
                    float v = sacc[nf][r01 * 2 + c] * 0.125f;
                    if (m0 + nf * 8 + 2 * t + c >= MEM) v = -1e30f;
                    sacc[nf][r01 * 2 + c] = v;
                    mx = fmaxf(mx, v);
                }
            }
            mx = fmaxf(mx, __shfl_xor_sync(0xffffffffu, mx, 1));
            mx = fmaxf(mx, __shfl_xor_sync(0xffffffffu, mx, 2));
            float nm = fmaxf(rmax[r01], mx);
            float corr = __expf(rmax[r01] - nm);
            rmax[r01] = nm;
            float ps = 0.f;
            #pragma unroll
            for (int nf = 0; nf < 8; ++nf) {
                float p0 = __expf(sacc[nf][r01 * 2 + 0] - nm);
                float p1 = __expf(sacc[nf][r01 * 2 + 1] - nm);
                sacc[nf][r01 * 2 + 0] = p0;
                sacc[nf][r01 * 2 + 1] = p1;
                ps += p0 + p1;
                oacc[nf][r01 * 2 + 0] *= corr;
                oacc[nf][r01 * 2 + 1] *= corr;
            }
            ps += __shfl_xor_sync(0xffffffffu, ps, 1);
            ps += __shfl_xor_sync(0xffffffffu, ps, 2);
            rsum[r01] = rsum[r01] * corr + ps;
            int prow = qr + g + r01 * 8;
            #pragma unroll
            for (int nf = 0; nf < 8; ++nf)
                *(float2*)&Ps[prow * QS + nf * 8 + 2 * t] =
                    make_float2(sacc[nf][r01 * 2 + 0], sacc[nf][r01 * 2 + 1]);
        }
        __syncwarp();

        // ---- O += P V ----
        #pragma unroll
        for (int ks = 0; ks < 8; ++ks) {
            int k0 = ks * 8;
            uint32_t a0 = f2tf(Ps[(qr + g    ) * QS + k0 + t    ]);
            uint32_t a1 = f2tf(Ps[(qr + g + 8) * QS + k0 + t    ]);
            uint32_t a2 = f2tf(Ps[(qr + g    ) * QS + k0 + t + 4]);
            uint32_t a3 = f2tf(Ps[(qr + g + 8) * QS + k0 + t + 4]);
            #pragma unroll
            for (int nf = 0; nf < 8; ++nf) {
                uint32_t b0 = f2tf(Vs[(k0 + t    ) * VS + nf * 8 + g]);
                uint32_t b1 = f2tf(Vs[(k0 + t + 4) * VS + nf * 8 + g]);
                mma_tf32(oacc[nf], a0, a1, a2, a3, b0, b1);
            }
        }
    }

    #pragma unroll
    for (int r01 = 0; r01 < 2; ++r01) {
        float inv = 1.f / rsum[r01];
        int grow = b0 + qr + g + r01 * 8;
        #pragma unroll
        for (int nf = 0; nf < 8; ++nf) {
            float2 o = make_float2(oacc[nf][r01 * 2 + 0] * inv,
                                   oacc[nf][r01 * 2 + 1] * inv);
            *(float2*)(ctx + (size_t)grow * 512 + h * 64 + nf * 8 + 2 * t) = o;
        }
    }
}

// ==================== LayerNorm ====================
__global__ void __launch_bounds__(128) ln_kernel(
    const float* __restrict__ x, const float* __restrict__ g,
    const float* __restrict__ b, float* __restrict__ y)
{
    const int row = blockIdx.x;
    const int tid = threadIdx.x;
    float4 v = *(const float4*)(x + (size_t)row * 512 + tid * 4);

    __shared__ float red[4];
    float s = v.x + v.y + v.z + v.w;
    #pragma unroll
    for (int o = 16; o > 0; o >>= 1) s += __shfl_xor_sync(0xffffffffu, s, o);
    if ((tid & 31) == 0) red[tid >> 5] = s;
    __syncthreads();
    float mean = (red[0] + red[1] + red[2] + red[3]) * (1.f / 512.f);
    __syncthreads();

    float dx = v.x - mean, dy = v.y - mean, dz = v.z - mean, dw = v.w - mean;
    float ss = dx * dx + dy * dy + dz * dz + dw * dw;
    #pragma unroll
    for (int o = 16; o > 0; o >>= 1) ss += __shfl_xor_sync(0xffffffffu, ss, o);
    if ((tid & 31) == 0) red[tid >> 5] = ss;
    __syncthreads();
    float var = (red[0] + red[1] + red[2] + red[3]) * (1.f / 512.f);
    float inv = rsqrtf(var + 1e-5f);

    float4 gg = *(const float4*)(g + tid * 4);
    float4 bb = *(const float4*)(b + tid * 4);
    float4 o;
    o.x = dx * inv * gg.x + bb.x;
    o.y = dy * inv * gg.y + bb.y;
    o.z = dz * inv * gg.z + bb.z;
    o.w = dw * inv * gg.w + bb.w;
    *(float4*)(y + (size_t)row * 512 + tid * 4) = o;
}

// ==================== mask compaction + memory EMA ====================
__global__ void __launch_bounds__(256) compact_kernel(
    const float* __restrict__ quality, int* __restrict__ midx, int* __restrict__ mcount)
{
    const int tid = threadIdx.x;
    const int base = tid * 32;
    int cnt = 0;
    for (int i = 0; i < 32; ++i) cnt += (quality[base + i] > 0.7f) ? 1 : 0;
    __shared__ int sc[256];
    __shared__ int offs[256];
    sc[tid] = cnt;
    __syncthreads();
    if (tid == 0) {
        int run = 0;
        for (int t = 0; t < 256; ++t) { offs[t] = run; run += sc[t]; }
        *mcount = run;
    }
    __syncthreads();
    int o = offs[tid];
    for (int i = 0; i < 32; ++i)
        if (quality[base + i] > 0.7f) midx[o++] = base + i;
}

__global__ void __launch_bounds__(128) memupd_kernel(
    const float* __restrict__ wm, const float* __restrict__ ns,
    const int* __restrict__ upd, const int* __restrict__ midx,
    const int* __restrict__ mcount, float* __restrict__ outmem)
{
    const int m = blockIdx.x;
    const int d = threadIdx.x * 4;
    float4 v = *(const float4*)(wm + (size_t)m * 512 + d);
    const int cnt = *mcount;
    for (int jj = 0; jj < cnt; ++jj) {
        int i = midx[jj];
        if (upd[i] == m) {
            float4 s = *(const float4*)(ns + (size_t)i * 512 + d);
            v.x = 0.9f * v.x + 0.1f * s.x;
            v.y = 0.9f * v.y + 0.1f * s.y;
            v.z = 0.9f * v.z + 0.1f * s.z;
            v.w = 0.9f * v.w + 0.1f * s.w;
        }
    }
    *(float4*)(outmem + (size_t)m * 512 + d) = v;
}

// ==================== host launcher ====================
extern "C" void kernel_launch(void* const* d_in, const int* in_sizes, int n_in,
                              void* d_out, int out_size)
{
    const float* obs    = (const float*)d_in[0];
    const float* ego    = (const float*)d_in[1];
    const float* wm     = (const float*)d_in[2];
    const float* enc_w1 = (const float*)d_in[3];
    const float* enc_b1 = (const float*)d_in[4];
    const float* enc_g  = (const float*)d_in[5];
    const float* enc_be = (const float*)d_in[6];
    const float* enc_w2 = (const float*)d_in[7];
    const float* enc_b2 = (const float*)d_in[8];
    const float* wq     = (const float*)d_in[9];
    const float* bq     = (const float*)d_in[10];
    const float* wk     = (const float*)d_in[11];
    const float* bk     = (const float*)d_in[12];
    const float* wv     = (const float*)d_in[13];
    const float* bv     = (const float*)d_in[14];
    const float* wo     = (const float*)d_in[15];
    const float* bo     = (const float*)d_in[16];
    const float* tr_w1  = (const float*)d_in[17];
    const float* tr_b1  = (const float*)d_in[18];
    const float* tr_g   = (const float*)d_in[19];
    const float* tr_be  = (const float*)d_in[20];
    const float* tr_w2  = (const float*)d_in[21];
    const float* tr_b2  = (const float*)d_in[22];
    const float* q_w1   = (const float*)d_in[23];
    const float* q_b1   = (const float*)d_in[24];
    const float* q_w2   = (const float*)d_in[25];
    const float* q_b2   = (const float*)d_in[26];
    const int*   uidx   = (const int*)d_in[27];

    float* out        = (float*)d_out;
    float* next_state = out;
    float* quality    = out + (size_t)BATCH * DIM;
    float* outmem     = quality + BATCH;

    float *h, *hn, *enc, *qb, *ctx, *fused, *kb, *vb;
    int *midx, *mcount;
    cudaGetSymbolAddress((void**)&h,      g_h);
    cudaGetSymbolAddress((void**)&hn,     g_hn);
    cudaGetSymbolAddress((void**)&enc,    g_enc);
    cudaGetSymbolAddress((void**)&qb,     g_q);
    cudaGetSymbolAddress((void**)&ctx,    g_ctx);
    cudaGetSymbolAddress((void**)&fused,  g_fused);
    cudaGetSymbolAddress((void**)&kb,     g_k);
    cudaGetSymbolAddress((void**)&vb,     g_v);
    cudaGetSymbolAddress((void**)&midx,   g_midx);
    cudaGetSymbolAddress((void**)&mcount, g_mcount);

    cudaFuncSetAttribute(gemm_mma<0>, cudaFuncAttributeMaxDynamicSharedMemorySize, GEMM_SMEM);
    cudaFuncSetAttribute(gemm_mma<1>, cudaFuncAttributeMaxDynamicSharedMemorySize, GEMM_SMEM);
    cudaFuncSetAttribute(gemm_mma<2>, cudaFuncAttributeMaxDynamicSharedMemorySize, GEMM_SMEM);
    cudaFuncSetAttribute(gemm_mma<3>, cudaFuncAttributeMaxDynamicSharedMemorySize, GEMM_SMEM);
    cudaFuncSetAttribute(attn_mma,    cudaFuncAttributeMaxDynamicSharedMemorySize, ATT_SMEM);

    dim3 gBig(4, 64), gMem(4, 8), gQual(1, 64);

    // encoder
    gemm_mma<1><<<gBig, 256, GEMM_SMEM>>>(obs, nullptr, enc_w1, enc_b1,
        nullptr, nullptr, nullptr, h, BATCH, 512, 16);
    ln_kernel<<<BATCH, 128>>>(h, enc_g, enc_be, hn);
    gemm_mma<0><<<gBig, 256, GEMM_SMEM>>>(hn, nullptr, enc_w2, enc_b2,
        nullptr, nullptr, nullptr, enc, BATCH, 512, 16);
    // projections
    gemm_mma<0><<<gBig, 256, GEMM_SMEM>>>(enc, nullptr, wq, bq,
        nullptr, nullptr, nullptr, qb, BATCH, 512, 16);
    gemm_mma<0><<<gMem, 256, GEMM_SMEM>>>(wm, nullptr, wk, bk,
        nullptr, nullptr, nullptr, kb, MEM, 512, 16);
    gemm_mma<0><<<gMem, 256, GEMM_SMEM>>>(wm, nullptr, wv, bv,
        nullptr, nullptr, nullptr, vb, MEM, 512, 16);
    // attention
    attn_mma<<<dim3(HEADS, BATCH / 128), 256, ATT_SMEM>>>(qb, kb, vb, ctx);
    // out projection + fuse
    gemm_mma<2><<<gBig, 256, GEMM_SMEM>>>(ctx, nullptr, wo, bo,
        enc, nullptr, nullptr, fused, BATCH, 512, 16);
    // transition (K=528, ego as zero-padded 17th chunk)
    gemm_mma<1><<<gBig, 256, GEMM_SMEM>>>(fused, ego, tr_w1, tr_b1,
        nullptr, nullptr, nullptr, h, BATCH, 528, 17);
    ln_kernel<<<BATCH, 128>>>(h, tr_g, tr_be, hn);
    gemm_mma<0><<<gBig, 256, GEMM_SMEM>>>(hn, nullptr, tr_w2, tr_b2,
        nullptr, nullptr, nullptr, next_state, BATCH, 512, 16);
    // quality head
    gemm_mma<3><<<gQual, 256, GEMM_SMEM>>>(next_state, nullptr, q_w1, q_b1,
        nullptr, q_w2, q_b2, quality, BATCH, 512, 16);
    // memory bank update
    compact_kernel<<<1, 256>>>(quality, midx, mcount);
    memupd_kernel<<<MEM, 128>>>(wm, next_state, uidx, midx, mcount, outmem);
}

// round 4
// speedup vs baseline: 3.6715x; 1.0132x over previous
#include <cuda_runtime.h>
#include <math.h>
#include <stdint.h>

#define BATCH 8192
#define DIM   512
#define MEM   1000
#define MEMP  1024
#define HEADS 8
#define DH    64

// ==================== helpers ====================
__device__ __forceinline__ uint32_t smem_u32(const void* p) {
    uint32_t a;
    asm("{ .reg .u64 t; cvta.to.shared.u64 t, %1; cvt.u32.u64 %0, t; }" : "=r"(a) : "l"(p));
    return a;
}
__device__ __forceinline__ uint32_t f2tf(float x) {
    uint32_t u; asm("cvt.rna.tf32.f32 %0, %1;" : "=r"(u) : "f"(x)); return u;
}
__device__ __forceinline__ float f2tf_f(float x) { return __uint_as_float(f2tf(x)); }
__device__ __forceinline__ void mma_tf32(float* c, uint32_t a0, uint32_t a1,
                                         uint32_t a2, uint32_t a3,
                                         uint32_t b0, uint32_t b1) {
    asm volatile(
        "mma.sync.aligned.m16n8k8.row.col.f32.tf32.tf32.f32 "
        "{%0,%1,%2,%3}, {%4,%5,%6,%7}, {%8,%9}, {%0,%1,%2,%3};"
        : "+f"(c[0]), "+f"(c[1]), "+f"(c[2]), "+f"(c[3])
        : "r"(a0), "r"(a1), "r"(a2), "r"(a3), "r"(b0), "r"(b1));
}
__device__ __forceinline__ void cp_async16(uint32_t dst, const void* src, int srcsize) {
    asm volatile("cp.async.cg.shared.global [%0], [%1], 16, %2;"
                 :: "r"(dst), "l"(src), "r"(srcsize));
}
#define CP_COMMIT() asm volatile("cp.async.commit_group;" ::: "memory")
#define CP_WAIT(N)  asm volatile("cp.async.wait_group %0;" :: "n"(N) : "memory")

// ==================== scratch ====================
__device__ float g_h[BATCH*DIM];        // fp32 pre-LN
__device__ float g_hn[BATCH*DIM];       // tf32
__device__ float g_enc[BATCH*DIM];      // fp32 (F for fuse)
__device__ float g_enc_t[BATCH*DIM];    // tf32 (A of wq gemm)
__device__ float g_q[BATCH*DIM];        // tf32
__device__ float g_ctx[BATCH*DIM];      // tf32
__device__ float g_fused[BATCH*DIM];    // tf32
__device__ float g_ns_t[BATCH*DIM];     // tf32 copy of next_state
__device__ float g_k[MEMP*DIM];         // tf32
__device__ float g_v[MEMP*DIM];         // tf32
__device__ float g_obs_t[BATCH*DIM];    // tf32
__device__ float g_ego_t[BATCH*16];     // tf32
__device__ float g_wm_t[MEM*DIM];       // tf32
// weights (tf32), concatenated
#define W_ENC1 0
#define W_ENC2 262144
#define W_WQ   524288
#define W_WK   786432
#define W_WV   1048576
#define W_WO   1310720
#define W_TR1  1572864
#define W_TR2  1843200
#define W_Q1   2105344
#define W_TOT  2170880
__device__ float g_w_t[W_TOT];
__device__ int   g_midx[BATCH];
__device__ int   g_mcount;

// ==================== prep: fp32 -> tf32-rounded fp32 ====================
struct PrepArgs {
    const float* src[12];
    float*       dst[12];
    int          n4[12];
};
__global__ void __launch_bounds__(256) prep_kernel(PrepArgs p) {
    int seg = blockIdx.y;
    int n4 = p.n4[seg];
    const float4* s = (const float4*)p.src[seg];
    float4* d = (float4*)p.dst[seg];
    for (int i = blockIdx.x * 256 + threadIdx.x; i < n4; i += gridDim.x * 256) {
        float4 v = s[i];
        float4 o;
        o.x = f2tf_f(v.x); o.y = f2tf_f(v.y);
        o.z = f2tf_f(v.z); o.w = f2tf_f(v.w);
        d[i] = o;
    }
}

// ==================== tf32 mma GEMM (operands pre-rounded) ====================
// C[i,j] = sum_k A[i,k]*W[j,k] (+bias). CTA tile 128 x NT, BK=32, double buffer.
// 8 warps as 2 (rows of 64) x 4 (cols of NT/4). Warp tile 64 x NT/4.
// EPI: 0 f32, 1 relu f32, 2 fuse->tf32, 3 quality, 4 tf32, 5 dual (f32 C + tf32 C2)
#define GS 36
template<int NT, int EPI>
__global__ void __launch_bounds__(256) gemm_mma(
    const float* __restrict__ A, const float* __restrict__ A2,
    const float* __restrict__ W, const float* __restrict__ bias,
    const float* __restrict__ F, const float* __restrict__ w2,
    const float* __restrict__ b2, float* __restrict__ C, float* __restrict__ C2,
    int Mrows, int Kw, int Ktiles)
{
    constexpr int NF  = NT / 32;           // n-fragments per warp
    constexpr int ASZ = 128 * GS;          // floats per A buffer
    constexpr int WSZ = NT * GS;
    extern __shared__ float sm[];
    float* Asm = sm;                       // 2 x ASZ
    float* Wsm = sm + 2 * ASZ;             // 2 x WSZ
    const uint32_t sA = smem_u32(Asm);
    const uint32_t sW = smem_u32(Wsm);

    const int tid = threadIdx.x;
    const int wid = tid >> 5, lane = tid & 31;
    const int g = lane >> 2, t = lane & 3;
    const int wm = wid & 1, wn = wid >> 1;
    const int row0 = blockIdx.y * 128;
    const int col0 = blockIdx.x * NT;

    float acc[4][NF][4];
    #pragma unroll
    for (int mf = 0; mf < 4; ++mf)
        #pragma unroll
        for (int nf = 0; nf < NF; ++nf)
            #pragma unroll
            for (int c = 0; c < 4; ++c) acc[mf][nf][c] = 0.f;

    auto load_chunk = [&](int ct, int buf) {
        const int kbase = ct * 32;
        constexpr int NLOAD = (1024 + NT * 8) / 256;
        #pragma unroll
        for (int it = 0; it < NLOAD; ++it) {
            int vid = tid + it * 256;
            if (vid < 1024) {
                int r = vid >> 3, q = vid & 7;
                int kel = kbase + q * 4;
                int grow = row0 + r;
                const float* src = A;
                int sz = 0;
                if (grow < Mrows) {
                    if (kel < 512) { src = A + (size_t)grow * 512 + kel; sz = 16; }
                    else if (A2 != nullptr && kel < 528) {
                        src = A2 + (size_t)grow * 16 + (kel - 512); sz = 16;
                    }
                }
                cp_async16(sA + (buf * ASZ + r * GS + q * 4) * 4, src, sz);
            } else {
                int vid2 = vid - 1024;
                int r = vid2 >> 3, q = vid2 & 7;
                int kel = kbase + q * 4;
                const float* src = W + (size_t)(col0 + r) * Kw + kel;
                int sz = (kel < Kw) ? 16 : 0;
                cp_async16(sW + (buf * WSZ + r * GS + q * 4) * 4, src, sz);
            }
        }
        CP_COMMIT();
    };

    load_chunk(0, 0);

    for (int ct = 0; ct < Ktiles; ++ct) {
        const int buf = ct & 1;
        if (ct + 1 < Ktiles) { load_chunk(ct + 1, (ct + 1) & 1); CP_WAIT(1); }
        else                 { CP_WAIT(0); }
        __syncthreads();

        const float* Ab = Asm + buf * ASZ + (wm * 64) * GS;
        const float* Wb = Wsm + buf * WSZ + (wn * (NT / 4)) * GS;
        #pragma unroll
        for (int ks = 0; ks < 4; ++ks) {
            const int k0 = ks * 8;
            uint32_t af[4][4];
            #pragma unroll
            for (int mf = 0; mf < 4; ++mf) {
                const float* ar = Ab + (mf * 16) * GS + k0;
                af[mf][0] = __float_as_uint(ar[(g    ) * GS + t    ]);
                af[mf][1] = __float_as_uint(ar[(g + 8) * GS + t    ]);
                af[mf][2] = __float_as_uint(ar[(g    ) * GS + t + 4]);
                af[mf][3] = __float_as_uint(ar[(g + 8) * GS + t + 4]);
            }
            #pragma unroll
            for (int nf = 0; nf < NF; ++nf) {
                const float* wr = Wb + (nf * 8 + g) * GS + k0;
                uint32_t b0 = __float_as_uint(wr[t]);
                uint32_t b1 = __float_as_uint(wr[t + 4]);
                #pragma unroll
                for (int mf = 0; mf < 4; ++mf)
                    mma_tf32(acc[mf][nf], af[mf][0], af[mf][1], af[mf][2], af[mf][3], b0, b1);
            }
        }
        __syncthreads();
    }

    if (EPI != 3) {
        #pragma unroll
        for (int mf = 0; mf < 4; ++mf) {
            #pragma unroll
            for (int r01 = 0; r01 < 2; ++r01) {
                int grow = row0 + wm * 64 + mf * 16 + g + r01 * 8;
                if (grow >= Mrows) continue;
                #pragma unroll
                for (int nf = 0; nf < NF; ++nf) {
                    int gcol = col0 + wn * (NT / 4) + nf * 8 + 2 * t;
                    float v0 = acc[mf][nf][r01 * 2 + 0] + bias[gcol];
                    float v1 = acc[mf][nf][r01 * 2 + 1] + bias[gcol + 1];
                    if (EPI == 1) { v0 = fmaxf(v0, 0.f); v1 = fmaxf(v1, 0.f); }
                    else if (EPI == 2) {
                        const float* fp = F + (size_t)grow * 512 + gcol;
                        v0 = 0.7f * fp[0] + 0.3f * v0;
                        v1 = 0.7f * fp[1] + 0.3f * v1;
                    }
                    if (EPI == 2 || EPI == 4) { v0 = f2tf_f(v0); v1 = f2tf_f(v1); }
                    *(float2*)(C + (size_t)grow * 512 + gcol) = make_float2(v0, v1);
                    if (EPI == 5)
                        *(float2*)(C2 + (size_t)grow * 512 + gcol) =
                            make_float2(f2tf_f(v0), f2tf_f(v1));
                }
            }
        }
    } else {
        // quality head (NT=128, col0=0): sigmoid(b2 + sum relu(acc+b1)*w2)
        float* qpart = sm;
        __syncthreads();
        #pragma unroll
        for (int mf = 0; mf < 4; ++mf) {
            #pragma unroll
            for (int r01 = 0; r01 < 2; ++r01) {
                float s = 0.f;
                #pragma unroll
                for (int nf = 0; nf < NF; ++nf) {
                    int c = wn * (NT / 4) + nf * 8 + 2 * t;
                    float h0 = fmaxf(acc[mf][nf][r01 * 2 + 0] + bias[c], 0.f);
                    float h1 = fmaxf(acc[mf][nf][r01 * 2 + 1] + bias[c + 1], 0.f);
                    s += h0 * w2[c] + h1 * w2[c + 1];
                }
                int rl = wm * 64 + mf * 16 + r01 * 8 + g;
                qpart[rl * 17 + wn * 4 + t] = s;
            }
        }
        __syncthreads();
        if (tid < 128) {
            float s = b2[0];
            #pragma unroll
            for (int i = 0; i < 16; ++i) s += qpart[tid * 17 + i];
            C[row0 + tid] = 1.f / (1.f + expf(-s));
        }
    }
}
#define GEMM_SMEM(NT) ((2 * 128 * GS + 2 * (NT) * GS) * 4)

// ==================== tf32 mma flash attention (operands pre-rounded) =========
#define QS 68
#define VS 72
#define ATT_SMEM ((128*QS + 64*QS + 128*QS + 64*VS) * 4)
__global__ void __launch_bounds__(256) attn_mma(
    const float* __restrict__ Q, const float* __restrict__ Kb,
    const float* __restrict__ Vb, float* __restrict__ ctx)
{
    extern __shared__ float sm[];
    float* Qs = sm;                       // 128 x 68 (tf32 bits)
    float* Ks = Qs + 128 * QS;            // 64 x 68
    float* Ps = Ks + 64 * QS;             // 128 x 68 (tf32 bits)
    float* Vs = Ps + 128 * QS;            // 64 x 72
    const uint32_t sK = smem_u32(Ks);
    const uint32_t sV = smem_u32(Vs);

    const int h = blockIdx.x;
    const int b0 = blockIdx.y * 128;
    const int tid = threadIdx.x;
    const int wid = tid >> 5, lane = tid & 31;
    const int g = lane >> 2, t = lane & 3;
    const int qr = wid * 16;

    #pragma unroll
    for (int it = 0; it < 8; ++it) {
        int vid = tid + it * 256;
        int r = vid >> 4, q = vid & 15;
        float4 v = *(const float4*)(Q + (size_t)(b0 + r) * 512 + h * 64 + q * 4);
        *(float4*)&Qs[r * QS + q * 4] = v;
    }

    float oacc[8][4];
    float rmax[2] = {-1e30f, -1e30f}, rsum[2] = {0.f, 0.f};
    #pragma unroll
    for (int nf = 0; nf < 8; ++nf)
        #pragma unroll
        for (int c = 0; c < 4; ++c) oacc[nf][c] = 0.f;

    for (int m0 = 0; m0 < MEMP; m0 += 64) {
        __syncthreads();
        #pragma unroll
        for (int it = 0; it < 4; ++it) {
            int vid = tid + it * 256;
            int r = vid >> 4, q = vid & 15;
            int gm = m0 + r;
            int sz = (gm < MEM) ? 16 : 0;
            cp_async16(sK + (r * QS + q * 4) * 4, Kb + (size_t)gm * 512 + h * 64 + q * 4, sz);
            cp_async16(sV + (r * VS + q * 4) * 4, Vb + (size_t)gm * 512 + h * 64 + q * 4, sz);
        }
        CP_COMMIT();
        CP_WAIT(0);
        __syncthreads();

        // ---- S = Q K^T ----
        float sacc[8][4];
        #pragma unroll
        for (int nf = 0; nf < 8; ++nf)
            #pragma unroll
            for (int c = 0; c < 4; ++c) sacc[nf][c] = 0.f;
        #pragma unroll
        for (int ks = 0; ks < 8; ++ks) {
            int k0 = ks * 8;
            uint32_t a0 = __float_as_uint(Qs[(qr + g    ) * QS + k0 + t    ]);
            uint32_t a1 = __float_as_uint(Qs[(qr + g + 8) * QS + k0 + t    ]);
            uint32_t a2 = __float_as_uint(Qs[(qr + g    ) * QS + k0 + t + 4]);
            uint32_t a3 = __float_as_uint(Qs[(qr + g + 8) * QS + k0 + t + 4]);
            #pragma unroll
            for (int nf = 0; nf < 8; ++nf) {
                uint32_t b0 = __float_as_uint(Ks[(nf * 8 + g) * QS + k0 + t    ]);
                uint32_t b1 = __float_as_uint(Ks[(nf * 8 + g) * QS + k0 + t + 4]);
                mma_tf32(sacc[nf], a0, a1, a2, a3, b0, b1);
            }
        }

        // ---- online softmax; P -> Ps (tf32-rounded, warp-private rows) ----
        #pragma unroll
        for (int r01 = 0; r01 < 2; ++r01) {
            float mx = -1e30f;
            #pragma unroll
            for (int nf = 0; nf < 8; ++nf) {
                #pragma unroll
                for (int c = 0; c < 2; ++c) {
                    float v = sacc[nf][r01 * 2 + c] * 0.125f;
                    if (m0 + nf * 8 + 2 * t + c >= MEM) v = -1e30f;
                    sacc[nf][r01 * 2 + c] = v;
                    mx = fmaxf(mx, v);
                }
            }
            mx = fmaxf(mx, __shfl_xor_sync(0xffffffffu, mx, 1));
            mx = fmaxf(mx, __shfl_xor_sync(0xffffffffu, mx, 2));
            float nm = fmaxf(rmax[r01], mx);
            float corr = __expf(rmax[r01] - nm);
            rmax[r01] = nm;
            float ps = 0.f;
            #pragma unroll
            for (int nf = 0; nf < 8; ++nf) {
                float p0 = __expf(sacc[nf][r01 * 2 + 0] - nm);
                float p1 = __expf(sacc[nf][r01 * 2 + 1] - nm);
                sacc[nf][r01 * 2 + 0] = p0;
                sacc[nf][r01 * 2 + 1] = p1;
                ps += p0 + p1;
                oacc[nf][r01 * 2 + 0] *= corr;
                oacc[nf][r01 * 2 + 1] *= corr;
            }
            ps += __shfl_xor_sync(0xffffffffu, ps, 1);
            ps += __shfl_xor_sync(0xffffffffu, ps, 2);
            rsum[r01] = rsum[r01] * corr + ps;
            int prow = qr + g + r01 * 8;
            #pragma unroll
            for (int nf = 0; nf < 8; ++nf)
                *(float2*)&Ps[prow * QS + nf * 8 + 2 * t] =
                    make_float2(f2tf_f(sacc[nf][r01 * 2 + 0]),
                                f2tf_f(sacc[nf][r01 * 2 + 1]));
        }
        __syncwarp();

        // ---- O += P V ----
        #pragma unroll
        for (int ks = 0; ks < 8; ++ks) {
            int k0 = ks * 8;
            uint32_t a0 = __float_as_uint(Ps[(qr + g    ) * QS + k0 + t    ]);
            uint32_t a1 = __float_as_uint(Ps[(qr + g + 8) * QS + k0 + t    ]);
            uint32_t a2 = __float_as_uint(Ps[(qr + g    ) * QS + k0 + t + 4]);
            uint32_t a3 = __float_as_uint(Ps[(qr + g + 8) * QS + k0 + t + 4]);
            #pragma unroll
            for (int nf = 0; nf < 8; ++nf) {
                uint32_t b0 = __float_as_uint(Vs[(k0 + t    ) * VS + nf * 8 + g]);
                uint32_t b1 = __float_as_uint(Vs[(k0 + t + 4) * VS + nf * 8 + g]);
                mma_tf32(oacc[nf], a0, a1, a2, a3, b0, b1);
            }
        }
    }

    #pragma unroll
    for (int r01 = 0; r01 < 2; ++r01) {
        float inv = 1.f / rsum[r01];
        int grow = b0 + qr + g + r01 * 8;
        #pragma unroll
        for (int nf = 0; nf < 8; ++nf) {
            float2 o = make_float2(f2tf_f(oacc[nf][r01 * 2 + 0] * inv),
                                   f2tf_f(oacc[nf][r01 * 2 + 1] * inv));
            *(float2*)(ctx + (size_t)grow * 512 + h * 64 + nf * 8 + 2 * t) = o;
        }
    }
}

// ==================== LayerNorm (tf32 output) ====================
__global__ void __launch_bounds__(128) ln_kernel(
    const float* __restrict__ x, const float* __restrict__ g,
    const float* __restrict__ b, float* __restrict__ y)
{
    const int row = blockIdx.x;
    const int tid = threadIdx.x;
    float4 v = *(const float4*)(x + (size_t)row * 512 + tid * 4);

    __shared__ float red[4];
    float s = v.x + v.y + v.z + v.w;
    #pragma unroll
    for (int o = 16; o > 0; o >>= 1) s += __shfl_xor_sync(0xffffffffu, s, o);
    if ((tid & 31) == 0) red[tid >> 5] = s;
    __syncthreads();
    float mean = (red[0] + red[1] + red[2] + red[3]) * (1.f / 512.f);
    __syncthreads();

    float dx = v.x - mean, dy = v.y - mean, dz = v.z - mean, dw = v.w - mean;
    float ss = dx * dx + dy * dy + dz * dz + dw * dw;
    #pragma unroll
    for (int o = 16; o > 0; o >>= 1) ss += __shfl_xor_sync(0xffffffffu, ss, o);
    if ((tid & 31) == 0) red[tid >> 5] = ss;
    __syncthreads();
    float var = (red[0] + red[1] + red[2] + red[3]) * (1.f / 512.f);
    float inv = rsqrtf(var + 1e-5f);

    float4 gg = *(const float4*)(g + tid * 4);
    float4 bb = *(const float4*)(b + tid * 4);
    float4 o;
    o.x = f2tf_f(dx * inv * gg.x + bb.x);
    o.y = f2tf_f(dy * inv * gg.y + bb.y);
    o.z = f2tf_f(dz * inv * gg.z + bb.z);
    o.w = f2tf_f(dw * inv * gg.w + bb.w);
    *(float4*)(y + (size_t)row * 512 + tid * 4) = o;
}

// ==================== mask compaction + memory EMA ====================
__global__ void __launch_bounds__(256) compact_kernel(
    const float* __restrict__ quality, int* __restrict__ midx, int* __restrict__ mcount)
{
    const int tid = threadIdx.x;
    const int base = tid * 32;
    int cnt = 0;
    for (int i = 0; i < 32; ++i) cnt += (quality[base + i] > 0.7f) ? 1 : 0;
    __shared__ int sc[256];
    __shared__ int offs[256];
    sc[tid] = cnt;
    __syncthreads();
    if (tid == 0) {
        int run = 0;
        for (int t = 0; t < 256; ++t) { offs[t] = run; run += sc[t]; }
        *mcount = run;
    }
    __syncthreads();
    int o = offs[tid];
    for (int i = 0; i < 32; ++i)
        if (quality[base + i] > 0.7f) midx[o++] = base + i;
}

__global__ void __launch_bounds__(128) memupd_kernel(
    const float* __restrict__ wm, const float* __restrict__ ns,
    const int* __restrict__ upd, const int* __restrict__ midx,
    const int* __restrict__ mcount, float* __restrict__ outmem)
{
    const int m = blockIdx.x;
    const int d = threadIdx.x * 4;
    float4 v = *(const float4*)(wm + (size_t)m * 512 + d);
    const int cnt = *mcount;
    for (int jj = 0; jj < cnt; ++jj) {
        int i = midx[jj];
        if (upd[i] == m) {
            float4 s = *(const float4*)(ns + (size_t)i * 512 + d);
            v.x = 0.9f * v.x + 0.1f * s.x;
            v.y = 0.9f * v.y + 0.1f * s.y;
            v.z = 0.9f * v.z + 0.1f * s.z;
            v.w = 0.9f * v.w + 0.1f * s.w;
        }
    }
    *(float4*)(outmem + (size_t)m * 512 + d) = v;
}

// ==================== host launcher ====================
extern "C" void kernel_launch(void* const* d_in, const int* in_sizes, int n_in,
                              void* d_out, int out_size)
{
    const float* obs    = (const float*)d_in[0];
    const float* ego    = (const float*)d_in[1];
    const float* wm     = (const float*)d_in[2];
    const float* enc_w1 = (const float*)d_in[3];
    const float* enc_b1 = (const float*)d_in[4];
    const float* enc_g  = (const float*)d_in[5];
    const float* enc_be = (const float*)d_in[6];
    const float* enc_w2 = (const float*)d_in[7];
    const float* enc_b2 = (const float*)d_in[8];
    const float* wq     = (const float*)d_in[9];
    const float* bq     = (const float*)d_in[10];
    const float* wk     = (const float*)d_in[11];
    const float* bk     = (const float*)d_in[12];
    const float* wv     = (const float*)d_in[13];
    const float* bv     = (const float*)d_in[14];
    const float* wo     = (const float*)d_in[15];
    const float* bo     = (const float*)d_in[16];
    const float* tr_w1  = (const float*)d_in[17];
    const float* tr_b1  = (const float*)d_in[18];
    const float* tr_g   = (const float*)d_in[19];
    const float* tr_be  = (const float*)d_in[20];
    const float* tr_w2  = (const float*)d_in[21];
    const float* tr_b2  = (const float*)d_in[22];
    const float* q_w1   = (const float*)d_in[23];
    const float* q_b1   = (const float*)d_in[24];
    const float* q_w2   = (const float*)d_in[25];
    const float* q_b2   = (const float*)d_in[26];
    const int*   uidx   = (const int*)d_in[27];

    float* out        = (float*)d_out;
    float* next_state = out;
    float* quality    = out + (size_t)BATCH * DIM;
    float* outmem     = quality + BATCH;

    float *h, *hn, *enc, *enc_t, *qb, *ctx, *fused, *ns_t, *kb, *vb;
    float *obs_t, *ego_t, *wm_t, *w_t;
    int *midx, *mcount;
    cudaGetSymbolAddress((void**)&h,      g_h);
    cudaGetSymbolAddress((void**)&hn,     g_hn);
    cudaGetSymbolAddress((void**)&enc,    g_enc);
    cudaGetSymbolAddress((void**)&enc_t,  g_enc_t);
    cudaGetSymbolAddress((void**)&qb,     g_q);
    cudaGetSymbolAddress((void**)&ctx,    g_ctx);
    cudaGetSymbolAddress((void**)&fused,  g_fused);
    cudaGetSymbolAddress((void**)&ns_t,   g_ns_t);
    cudaGetSymbolAddress((void**)&kb,     g_k);
    cudaGetSymbolAddress((void**)&vb,     g_v);
    cudaGetSymbolAddress((void**)&obs_t,  g_obs_t);
    cudaGetSymbolAddress((void**)&ego_t,  g_ego_t);
    cudaGetSymbolAddress((void**)&wm_t,   g_wm_t);
    cudaGetSymbolAddress((void**)&w_t,    g_w_t);
    cudaGetSymbolAddress((void**)&midx,   g_midx);
    cudaGetSymbolAddress((void**)&mcount, g_mcount);

    cudaFuncSetAttribute(gemm_mma<256,1>, cudaFuncAttributeMaxDynamicSharedMemorySize, GEMM_SMEM(256));
    cudaFuncSetAttribute(gemm_mma<256,2>, cudaFuncAttributeMaxDynamicSharedMemorySize, GEMM_SMEM(256));
    cudaFuncSetAttribute(gemm_mma<256,4>, cudaFuncAttributeMaxDynamicSharedMemorySize, GEMM_SMEM(256));
    cudaFuncSetAttribute(gemm_mma<256,5>, cudaFuncAttributeMaxDynamicSharedMemorySize, GEMM_SMEM(256));
    cudaFuncSetAttribute(gemm_mma<128,3>, cudaFuncAttributeMaxDynamicSharedMemorySize, GEMM_SMEM(128));
    cudaFuncSetAttribute(attn_mma,        cudaFuncAttributeMaxDynamicSharedMemorySize, ATT_SMEM);

    // ---- prep: tf32-round inputs + weights ----
    PrepArgs pa;
    const float* srcs[12] = {obs, ego, wm, enc_w1, enc_w2, wq, wk, wv, wo, tr_w1, tr_w2, q_w1};
    float* dsts[12] = {obs_t, ego_t, wm_t,
                       w_t + W_ENC1, w_t + W_ENC2, w_t + W_WQ, w_t + W_WK, w_t + W_WV,
                       w_t + W_WO, w_t + W_TR1, w_t + W_TR2, w_t + W_Q1};
    int n4s[12] = {BATCH*DIM/4, BATCH*16/4, MEM*DIM/4,
                   262144/4, 262144/4, 262144/4, 262144/4, 262144/4,
                   262144/4, 270336/4, 262144/4, 65536/4};
    for (int i = 0; i < 12; ++i) { pa.src[i] = srcs[i]; pa.dst[i] = dsts[i]; pa.n4[i] = n4s[i]; }
    prep_kernel<<<dim3(512, 12), 256>>>(pa);

    dim3 gBig(2, 64), gMem(2, 8), gQual(1, 64);

    // encoder
    gemm_mma<256,1><<<gBig, 256, GEMM_SMEM(256)>>>(obs_t, nullptr, w_t + W_ENC1, enc_b1,
        nullptr, nullptr, nullptr, h, nullptr, BATCH, 512, 16);
    ln_kernel<<<BATCH, 128>>>(h, enc_g, enc_be, hn);
    gemm_mma<256,5><<<gBig, 256, GEMM_SMEM(256)>>>(hn, nullptr, w_t + W_ENC2, enc_b2,
        nullptr, nullptr, nullptr, enc, enc_t, BATCH, 512, 16);
    // projections
    gemm_mma<256,4><<<gBig, 256, GEMM_SMEM(256)>>>(enc_t, nullptr, w_t + W_WQ, bq,
        nullptr, nullptr, nullptr, qb, nullptr, BATCH, 512, 16);
    gemm_mma<256,4><<<gMem, 256, GEMM_SMEM(256)>>>(wm_t, nullptr, w_t + W_WK, bk,
        nullptr, nullptr, nullptr, kb, nullptr, MEM, 512, 16);
    gemm_mma<256,4><<<gMem, 256, GEMM_SMEM(256)>>>(wm_t, nullptr, w_t + W_WV, bv,
        nullptr, nullptr, nullptr, vb, nullptr, MEM, 512, 16);
    // attention (tf32-out ctx)
    attn_mma<<<dim3(HEADS, BATCH / 128), 256, ATT_SMEM>>>(qb, kb, vb, ctx);
    // out projection + fuse -> tf32 fused
    gemm_mma<256,2><<<gBig, 256, GEMM_SMEM(256)>>>(ctx, nullptr, w_t + W_WO, bo,
        enc, nullptr, nullptr, fused, nullptr, BATCH, 512, 16);
    // transition
    gemm_mma<256,1><<<gBig, 256, GEMM_SMEM(256)>>>(fused, ego_t, w_t + W_TR1, tr_b1,
        nullptr, nullptr, nullptr, h, nullptr, BATCH, 528, 17);
    ln_kernel<<<BATCH, 128>>>(h, tr_g, tr_be, hn);
    gemm_mma<256,5><<<gBig, 256, GEMM_SMEM(256)>>>(hn, nullptr, w_t + W_TR2, tr_b2,
        nullptr, nullptr, nullptr, next_state, ns_t, BATCH, 512, 16);
    // quality head
    gemm_mma<128,3><<<gQual, 256, GEMM_SMEM(128)>>>(ns_t, nullptr, w_t + W_Q1, q_b1,
        nullptr, q_w2, q_b2, quality, nullptr, BATCH, 512, 16);
    // memory bank update
    compact_kernel<<<1, 256>>>(quality, midx, mcount);
    memupd_kernel<<<MEM, 128>>>(wm, next_state, uidx, midx, mcount, outmem);
}